// round 15
// baseline (speedup 1.0000x reference)
#include <cuda_runtime.h>

#define BB  2
#define SS  4096
#define HH  512
#define NHH 8
#define HDD 64

// ---------------- scratch (device globals; no cudaMalloc allowed) ----------
__device__ float g_Qh[(size_t)BB * NHH * SS * HDD];   // [B,NH,S,HD]
__device__ float g_Kh[(size_t)BB * NHH * SS * HDD];
__device__ float g_Vh[(size_t)BB * NHH * SS * HDD];
__device__ float g_X [(size_t)BB * SS * HH];          // attention out, flat [B,S,H]
__device__ float g_Y [(size_t)BB * SS * HH];          // final proj scratch if x not requested
__device__ float g_Linv[(size_t)BB * NHH * SS];       // 1/rowsum per attention row

// ---------------------------------------------------------------------------
// GEMM: out = A @ W^T + bias.  A:[8192,512] row-major, W:[512,512] row-major.
// headLayout=1: out[((b*NH+h)*S+s)*HD+d]  (h = blockIdx.y since tile width 64 == HD)
// headLayout=0: out[m*H + n] flat.
// 64x64 tile, 256 threads, 4x4 per thread, K-step 16.
// ---------------------------------------------------------------------------
__global__ void __launch_bounds__(256)
gemm_bias_kernel(const float* __restrict__ A, const float* __restrict__ W,
                 const float* __restrict__ bias, float* __restrict__ out,
                 int headLayout)
{
    __shared__ float As[16 * 68];   // [k][m], padded stride 68 (16B-aligned rows)
    __shared__ float Ws[16 * 68];   // [k][n]

    const int tid = threadIdx.x;
    const int tx  = tid & 15;
    const int ty  = tid >> 4;
    const int m0  = blockIdx.x * 64;
    const int n0  = blockIdx.y * 64;
    const int lm  = tid >> 2;          // 0..63
    const int lk  = (tid & 3) << 2;    // 0,4,8,12

    float acc[4][4] = {};

    for (int k0 = 0; k0 < HH; k0 += 16) {
        float4 a = *(const float4*)&A[(size_t)(m0 + lm) * HH + k0 + lk];
        float4 w = *(const float4*)&W[(size_t)(n0 + lm) * HH + k0 + lk];
        __syncthreads();
        As[(lk + 0) * 68 + lm] = a.x; As[(lk + 1) * 68 + lm] = a.y;
        As[(lk + 2) * 68 + lm] = a.z; As[(lk + 3) * 68 + lm] = a.w;
        Ws[(lk + 0) * 68 + lm] = w.x; Ws[(lk + 1) * 68 + lm] = w.y;
        Ws[(lk + 2) * 68 + lm] = w.z; Ws[(lk + 3) * 68 + lm] = w.w;
        __syncthreads();
        #pragma unroll
        for (int kk = 0; kk < 16; kk++) {
            float4 av = *(const float4*)&As[kk * 68 + ty * 4];
            float4 wv = *(const float4*)&Ws[kk * 68 + tx * 4];
            float aa[4] = {av.x, av.y, av.z, av.w};
            float ww[4] = {wv.x, wv.y, wv.z, wv.w};
            #pragma unroll
            for (int i = 0; i < 4; i++)
                #pragma unroll
                for (int j = 0; j < 4; j++)
                    acc[i][j] += aa[i] * ww[j];
        }
    }

    float4 bv = *(const float4*)&bias[n0 + tx * 4];
    float ba[4] = {bv.x, bv.y, bv.z, bv.w};

    #pragma unroll
    for (int i = 0; i < 4; i++) {
        const int m = m0 + ty * 4 + i;
        float4 o = make_float4(acc[i][0] + ba[0], acc[i][1] + ba[1],
                               acc[i][2] + ba[2], acc[i][3] + ba[3]);
        if (headLayout) {
            const int b = m >> 12;          // m / 4096
            const int s = m & 4095;
            *(float4*)&out[(((size_t)(b * NHH + blockIdx.y)) * SS + s) * HDD + tx * 4] = o;
        } else {
            *(float4*)&out[(size_t)m * HH + n0 + tx * 4] = o;
        }
    }
}

// ---------------------------------------------------------------------------
// Attention: per block = one (b,h) x 64-query tile, sweep all 4096 keys in
// 64-wide K tiles.  Single pass (max-free softmax is exact: shift-invariant,
// |score| << 88 so exp never overflows).  Writes unnormalized exp scores to
// attn (normalized later), accumulates rowsum l and O = P @ V, writes O/l
// directly in flat [B,S,H] layout, and stores 1/l for the rescale kernel.
// smem: Qs[64][68] (d-major), KP[64][68] (K d-major, then reused for P
// row-major), Vs[64][64] (k-major rows of 64 d).
// AV loop is 4-key grouped: P rows read as broadcast LDS.128 (1 wavefront)
// instead of 4 scalar LDS.32 — cuts AV shared-op count 320 -> 128 per
// thread per K-tile (the L1 bottleneck seen in ncu: l1tex 88.8%).
// ---------------------------------------------------------------------------
__global__ void __launch_bounds__(256)
attn_kernel(float* __restrict__ attn)   // may be null -> skip attention stores
{
    extern __shared__ float sm[];
    float* Qs = sm;                 // Qs[d*68 + r]
    float* KP = sm + 64 * 68;       // scores: KP[d*68 + c] ; AV: KP[r*68 + k]
    float* Vs = sm + 2 * 64 * 68;   // Vs[k*64 + d]

    const int tid = threadIdx.x;
    const int tx  = tid & 15;
    const int ty  = tid >> 4;
    const int qt  = blockIdx.x;
    const int h   = blockIdx.y;
    const int b   = blockIdx.z;
    const int bh  = b * NHH + h;
    const int q0  = qt * 64;

    const float* __restrict__ Qg = g_Qh + ((size_t)bh * SS + q0) * HDD;
    const float* __restrict__ Kg = g_Kh + (size_t)bh * SS * HDD;
    const float* __restrict__ Vg = g_Vh + (size_t)bh * SS * HDD;

    // Q tile -> smem, transposed to d-major
    #pragma unroll
    for (int it = 0; it < 4; it++) {
        int idx = tid + it * 256;
        int r   = idx >> 4;
        int d0  = (idx & 15) << 2;
        float4 t = *(const float4*)&Qg[(size_t)r * HDD + d0];
        Qs[(d0 + 0) * 68 + r] = t.x;
        Qs[(d0 + 1) * 68 + r] = t.y;
        Qs[(d0 + 2) * 68 + r] = t.z;
        Qs[(d0 + 3) * 68 + r] = t.w;
    }

    float Oa[4][4] = {};
    float lsum[4]  = {};

    for (int kt = 0; kt < 64; kt++) {
        const int s0 = kt * 64;
        __syncthreads();   // prev AV done (and first iter: Q stores visible)

        // K tile transposed -> KP, V tile -> Vs
        #pragma unroll
        for (int it = 0; it < 4; it++) {
            int idx = tid + it * 256;
            int r   = idx >> 4;
            int d0  = (idx & 15) << 2;
            float4 t = *(const float4*)&Kg[(size_t)(s0 + r) * HDD + d0];
            KP[(d0 + 0) * 68 + r] = t.x;
            KP[(d0 + 1) * 68 + r] = t.y;
            KP[(d0 + 2) * 68 + r] = t.z;
            KP[(d0 + 3) * 68 + r] = t.w;
            float4 u = *(const float4*)&Vg[(size_t)(s0 + r) * HDD + d0];
            *(float4*)&Vs[r * 64 + d0] = u;
        }
        __syncthreads();

        // scores: S = Q K^T  (rank-1 updates over d; 2x LDS.128 + 16 FFMA)
        float p[4][4] = {};
        #pragma unroll 8
        for (int d = 0; d < 64; d++) {
            float4 qv = *(const float4*)&Qs[d * 68 + ty * 4];
            float4 kv = *(const float4*)&KP[d * 68 + tx * 4];
            float qa[4] = {qv.x, qv.y, qv.z, qv.w};
            float ka[4] = {kv.x, kv.y, kv.z, kv.w};
            #pragma unroll
            for (int i = 0; i < 4; i++)
                #pragma unroll
                for (int j = 0; j < 4; j++)
                    p[i][j] += qa[i] * ka[j];
        }

        // exp(scale * s), rowsum, unnormalized attention store
        #pragma unroll
        for (int i = 0; i < 4; i++) {
            #pragma unroll
            for (int j = 0; j < 4; j++)
                p[i][j] = __expf(p[i][j] * 0.125f);   // 1/sqrt(64)
            lsum[i] += p[i][0] + p[i][1] + p[i][2] + p[i][3];
            if (attn)
                *(float4*)&attn[((size_t)bh * SS + q0 + ty * 4 + i) * SS + s0 + tx * 4]
                    = make_float4(p[i][0], p[i][1], p[i][2], p[i][3]);
        }

        __syncthreads();   // everyone done reading K from KP
        #pragma unroll
        for (int i = 0; i < 4; i++)
            *(float4*)&KP[(ty * 4 + i) * 68 + tx * 4]
                = make_float4(p[i][0], p[i][1], p[i][2], p[i][3]);
        __syncthreads();

        // O += P @ V, grouped 4 keys per step:
        // pa[i] = P[row i][kk0..kk0+3] via one broadcast LDS.128 per row.
        #pragma unroll 4
        for (int kk0 = 0; kk0 < 64; kk0 += 4) {
            float pa[4][4];
            #pragma unroll
            for (int i = 0; i < 4; i++) {
                float4 pv = *(const float4*)&KP[(ty * 4 + i) * 68 + kk0];
                pa[i][0] = pv.x; pa[i][1] = pv.y; pa[i][2] = pv.z; pa[i][3] = pv.w;
            }
            #pragma unroll
            for (int t = 0; t < 4; t++) {
                float4 vv = *(const float4*)&Vs[(kk0 + t) * 64 + tx * 4];
                #pragma unroll
                for (int i = 0; i < 4; i++) {
                    Oa[i][0] += pa[i][t] * vv.x;
                    Oa[i][1] += pa[i][t] * vv.y;
                    Oa[i][2] += pa[i][t] * vv.z;
                    Oa[i][3] += pa[i][t] * vv.w;
                }
            }
        }
    }

    // reduce row sums across the 16 tx lanes (xor over lane bits 0..3 only)
    #pragma unroll
    for (int i = 0; i < 4; i++) {
        float v = lsum[i];
        #pragma unroll
        for (int off = 1; off < 16; off <<= 1)
            v += __shfl_xor_sync(0xffffffffu, v, off);
        lsum[i] = v;
    }

    #pragma unroll
    for (int i = 0; i < 4; i++) {
        const float rinv = 1.0f / lsum[i];
        if (tx == 0)
            g_Linv[(size_t)bh * SS + q0 + ty * 4 + i] = rinv;
        float4 o = make_float4(Oa[i][0] * rinv, Oa[i][1] * rinv,
                               Oa[i][2] * rinv, Oa[i][3] * rinv);
        *(float4*)&g_X[((size_t)b * SS + q0 + ty * 4 + i) * HH + h * HDD + tx * 4] = o;
    }
}

// ---------------------------------------------------------------------------
// Normalize attention in place: attn[row, :] *= 1/l[row]
// ---------------------------------------------------------------------------
__global__ void rescale_kernel(float4* __restrict__ attn)
{
    const size_t n4 = (size_t)BB * NHH * SS * (SS / 4);
    size_t i = (size_t)blockIdx.x * blockDim.x + threadIdx.x;
    const size_t stride = (size_t)gridDim.x * blockDim.x;
    for (; i < n4; i += stride) {
        const size_t row = i >> 10;          // / (SS/4)
        const float r = __ldg(&g_Linv[row]);
        float4 v = attn[i];
        v.x *= r; v.y *= r; v.z *= r; v.w *= r;
        attn[i] = v;
    }
}

// ---------------------------------------------------------------------------
extern "C" void kernel_launch(void* const* d_in, const int* in_sizes, int n_in,
                              void* d_out, int out_size)
{
    const float* q  = (const float*)d_in[0];
    const float* k  = (const float*)d_in[1];
    const float* v  = (const float*)d_in[2];
    const float* Wq = (const float*)d_in[3];
    const float* bq = (const float*)d_in[4];
    const float* Wk = (const float*)d_in[5];
    const float* bk = (const float*)d_in[6];
    const float* Wv = (const float*)d_in[7];
    const float* bv = (const float*)d_in[8];
    const float* Wo = (const float*)d_in[9];
    const float* bo = (const float*)d_in[10];

    float *pQ, *pK, *pV, *pX, *pY;
    cudaGetSymbolAddress((void**)&pQ, g_Qh);
    cudaGetSymbolAddress((void**)&pK, g_Kh);
    cudaGetSymbolAddress((void**)&pV, g_Vh);
    cudaGetSymbolAddress((void**)&pX, g_X);
    cudaGetSymbolAddress((void**)&pY, g_Y);

    const long long X_ELEMS = (long long)BB * SS * HH;                 // 4,194,304
    const long long A_ELEMS = (long long)BB * NHH * SS * (long long)SS; // 268,435,456
    const long long osz = (long long)out_size;

    float* xout = nullptr;
    float* attn = nullptr;
    if (osz >= X_ELEMS + A_ELEMS) {            // tuple (x, attention)
        xout = (float*)d_out;
        attn = (float*)d_out + X_ELEMS;
    } else if (osz == A_ELEMS) {               // attention only
        attn = (float*)d_out;
    } else {                                   // x only
        xout = (float*)d_out;
    }

    const dim3 gproj(128, 8);
    gemm_bias_kernel<<<gproj, 256>>>(q, Wq, bq, pQ, 1);
    gemm_bias_kernel<<<gproj, 256>>>(k, Wk, bk, pK, 1);
    gemm_bias_kernel<<<gproj, 256>>>(v, Wv, bv, pV, 1);

    cudaFuncSetAttribute(attn_kernel, cudaFuncAttributeMaxDynamicSharedMemorySize, 51200);
    attn_kernel<<<dim3(64, 8, 2), 256, 51200>>>(attn);

    gemm_bias_kernel<<<gproj, 256>>>(pX, Wo, bo, xout ? xout : pY, 0);

    if (attn)
        rescale_kernel<<<16384, 256>>>((float4*)attn);
}

// round 16
// speedup vs baseline: 1.0500x; 1.0500x over previous
#include <cuda_runtime.h>

#define BB  2
#define SS  4096
#define HH  512
#define NHH 8
#define HDD 64

// ---------------- f32x2 packed-math helpers (sm_103a FFMA2 path) -----------
// Each f32x2 lane does the identical RN fp32 FMA as scalar FFMA, so pairing
// accumulators along j keeps every accumulator's reduction order bitwise
// identical to the scalar version.
__device__ __forceinline__ unsigned long long ffma2(unsigned long long a,
                                                    unsigned long long b,
                                                    unsigned long long c) {
    unsigned long long d;
    asm("fma.rn.f32x2 %0, %1, %2, %3;" : "=l"(d) : "l"(a), "l"(b), "l"(c));
    return d;
}
__device__ __forceinline__ unsigned long long pack2(float lo, float hi) {
    unsigned long long d;
    asm("mov.b64 %0, {%1, %2};" : "=l"(d) : "f"(lo), "f"(hi));
    return d;
}
__device__ __forceinline__ void unpack2(unsigned long long d, float& lo, float& hi) {
    asm("mov.b64 {%0, %1}, %2;" : "=f"(lo), "=f"(hi) : "l"(d));
}

// ---------------- scratch (device globals; no cudaMalloc allowed) ----------
__device__ float g_Qh[(size_t)BB * NHH * SS * HDD];   // [B,NH,S,HD]
__device__ float g_Kh[(size_t)BB * NHH * SS * HDD];
__device__ float g_Vh[(size_t)BB * NHH * SS * HDD];
__device__ float g_X [(size_t)BB * SS * HH];          // attention out, flat [B,S,H]
__device__ float g_Y [(size_t)BB * SS * HH];          // final proj scratch if x not requested
__device__ float g_Linv[(size_t)BB * NHH * SS];       // 1/rowsum per attention row

// ---------------------------------------------------------------------------
// GEMM: out = A @ W^T + bias.  A:[8192,512] row-major, W:[512,512] row-major.
// headLayout=1: out[((b*NH+h)*S+s)*HD+d]  (h = blockIdx.y since tile width 64 == HD)
// headLayout=0: out[m*H + n] flat.
// 64x64 tile, 256 threads, 4x4 per thread, K-step 16, FFMA2 inner product.
// ---------------------------------------------------------------------------
__global__ void __launch_bounds__(256)
gemm_bias_kernel(const float* __restrict__ A, const float* __restrict__ W,
                 const float* __restrict__ bias, float* __restrict__ out,
                 int headLayout)
{
    __shared__ float As[16 * 68];   // [k][m], padded stride 68 (16B-aligned rows)
    __shared__ float Ws[16 * 68];   // [k][n]

    const int tid = threadIdx.x;
    const int tx  = tid & 15;
    const int ty  = tid >> 4;
    const int m0  = blockIdx.x * 64;
    const int n0  = blockIdx.y * 64;
    const int lm  = tid >> 2;          // 0..63
    const int lk  = (tid & 3) << 2;    // 0,4,8,12

    unsigned long long acc[4][2] = {};   // pairs over j: (j0,j1),(j2,j3)

    for (int k0 = 0; k0 < HH; k0 += 16) {
        float4 a = *(const float4*)&A[(size_t)(m0 + lm) * HH + k0 + lk];
        float4 w = *(const float4*)&W[(size_t)(n0 + lm) * HH + k0 + lk];
        __syncthreads();
        As[(lk + 0) * 68 + lm] = a.x; As[(lk + 1) * 68 + lm] = a.y;
        As[(lk + 2) * 68 + lm] = a.z; As[(lk + 3) * 68 + lm] = a.w;
        Ws[(lk + 0) * 68 + lm] = w.x; Ws[(lk + 1) * 68 + lm] = w.y;
        Ws[(lk + 2) * 68 + lm] = w.z; Ws[(lk + 3) * 68 + lm] = w.w;
        __syncthreads();
        #pragma unroll
        for (int kk = 0; kk < 16; kk++) {
            float4 av = *(const float4*)&As[kk * 68 + ty * 4];
            float4 wv = *(const float4*)&Ws[kk * 68 + tx * 4];
            unsigned long long w01 = pack2(wv.x, wv.y);
            unsigned long long w23 = pack2(wv.z, wv.w);
            float aa[4] = {av.x, av.y, av.z, av.w};
            #pragma unroll
            for (int i = 0; i < 4; i++) {
                unsigned long long ad = pack2(aa[i], aa[i]);
                acc[i][0] = ffma2(ad, w01, acc[i][0]);
                acc[i][1] = ffma2(ad, w23, acc[i][1]);
            }
        }
    }

    float4 bv = *(const float4*)&bias[n0 + tx * 4];
    float ba[4] = {bv.x, bv.y, bv.z, bv.w};

    #pragma unroll
    for (int i = 0; i < 4; i++) {
        const int m = m0 + ty * 4 + i;
        float c0, c1, c2, c3;
        unpack2(acc[i][0], c0, c1);
        unpack2(acc[i][1], c2, c3);
        float4 o = make_float4(c0 + ba[0], c1 + ba[1], c2 + ba[2], c3 + ba[3]);
        if (headLayout) {
            const int b = m >> 12;          // m / 4096
            const int s = m & 4095;
            *(float4*)&out[(((size_t)(b * NHH + blockIdx.y)) * SS + s) * HDD + tx * 4] = o;
        } else {
            *(float4*)&out[(size_t)m * HH + n0 + tx * 4] = o;
        }
    }
}

// ---------------------------------------------------------------------------
// Attention: per block = one (b,h) x 64-query tile, sweep all 4096 keys in
// 64-wide K tiles.  Single pass (max-free softmax is exact: shift-invariant,
// |score| << 88 so exp never overflows).  Writes unnormalized exp scores to
// attn (normalized later), accumulates rowsum l and O = P @ V, writes O/l
// directly in flat [B,S,H] layout, and stores 1/l for the rescale kernel.
// Both GEMM loops use fma.rn.f32x2 (FFMA2): halves fma-pipe instruction
// count — the measured bottleneck (scalar version ran at the exact 36 TF/s
// FFMA-3reg rt=2 roofline). Accumulator pairing is along j, so reduction
// order per accumulator is bitwise identical to the scalar kernel.
// ---------------------------------------------------------------------------
__global__ void __launch_bounds__(256)
attn_kernel(float* __restrict__ attn)   // may be null -> skip attention stores
{
    extern __shared__ float sm[];
    float* Qs = sm;                 // Qs[d*68 + r]
    float* KP = sm + 64 * 68;       // scores: KP[d*68 + c] ; AV: KP[r*68 + k]
    float* Vs = sm + 2 * 64 * 68;   // Vs[k*64 + d]

    const int tid = threadIdx.x;
    const int tx  = tid & 15;
    const int ty  = tid >> 4;
    const int qt  = blockIdx.x;
    const int h   = blockIdx.y;
    const int b   = blockIdx.z;
    const int bh  = b * NHH + h;
    const int q0  = qt * 64;

    const float* __restrict__ Qg = g_Qh + ((size_t)bh * SS + q0) * HDD;
    const float* __restrict__ Kg = g_Kh + (size_t)bh * SS * HDD;
    const float* __restrict__ Vg = g_Vh + (size_t)bh * SS * HDD;

    // Q tile -> smem, transposed to d-major
    #pragma unroll
    for (int it = 0; it < 4; it++) {
        int idx = tid + it * 256;
        int r   = idx >> 4;
        int d0  = (idx & 15) << 2;
        float4 t = *(const float4*)&Qg[(size_t)r * HDD + d0];
        Qs[(d0 + 0) * 68 + r] = t.x;
        Qs[(d0 + 1) * 68 + r] = t.y;
        Qs[(d0 + 2) * 68 + r] = t.z;
        Qs[(d0 + 3) * 68 + r] = t.w;
    }

    unsigned long long Op[4][2] = {};   // O accumulator pairs over j
    float lsum[4]  = {};

    for (int kt = 0; kt < 64; kt++) {
        const int s0 = kt * 64;
        __syncthreads();   // prev AV done (and first iter: Q stores visible)

        // K tile transposed -> KP, V tile -> Vs
        #pragma unroll
        for (int it = 0; it < 4; it++) {
            int idx = tid + it * 256;
            int r   = idx >> 4;
            int d0  = (idx & 15) << 2;
            float4 t = *(const float4*)&Kg[(size_t)(s0 + r) * HDD + d0];
            KP[(d0 + 0) * 68 + r] = t.x;
            KP[(d0 + 1) * 68 + r] = t.y;
            KP[(d0 + 2) * 68 + r] = t.z;
            KP[(d0 + 3) * 68 + r] = t.w;
            float4 u = *(const float4*)&Vg[(size_t)(s0 + r) * HDD + d0];
            *(float4*)&Vs[r * 64 + d0] = u;
        }
        __syncthreads();

        // scores: S = Q K^T  (rank-1 updates over d; FFMA2 pairs over j)
        unsigned long long pp[4][2] = {};
        #pragma unroll 8
        for (int d = 0; d < 64; d++) {
            float4 qv = *(const float4*)&Qs[d * 68 + ty * 4];
            float4 kv = *(const float4*)&KP[d * 68 + tx * 4];
            unsigned long long k01 = pack2(kv.x, kv.y);
            unsigned long long k23 = pack2(kv.z, kv.w);
            float qa[4] = {qv.x, qv.y, qv.z, qv.w};
            #pragma unroll
            for (int i = 0; i < 4; i++) {
                unsigned long long qd = pack2(qa[i], qa[i]);
                pp[i][0] = ffma2(qd, k01, pp[i][0]);
                pp[i][1] = ffma2(qd, k23, pp[i][1]);
            }
        }

        // exp(scale * s), rowsum, unnormalized attention store
        float p[4][4];
        #pragma unroll
        for (int i = 0; i < 4; i++) {
            unpack2(pp[i][0], p[i][0], p[i][1]);
            unpack2(pp[i][1], p[i][2], p[i][3]);
            #pragma unroll
            for (int j = 0; j < 4; j++)
                p[i][j] = __expf(p[i][j] * 0.125f);   // 1/sqrt(64)
            lsum[i] += p[i][0] + p[i][1] + p[i][2] + p[i][3];
            if (attn)
                *(float4*)&attn[((size_t)bh * SS + q0 + ty * 4 + i) * SS + s0 + tx * 4]
                    = make_float4(p[i][0], p[i][1], p[i][2], p[i][3]);
        }

        __syncthreads();   // everyone done reading K from KP
        #pragma unroll
        for (int i = 0; i < 4; i++)
            *(float4*)&KP[(ty * 4 + i) * 68 + tx * 4]
                = make_float4(p[i][0], p[i][1], p[i][2], p[i][3]);
        __syncthreads();

        // O += P @ V, grouped 4 keys per step; FFMA2 pairs over j.
        #pragma unroll 4
        for (int kk0 = 0; kk0 < 64; kk0 += 4) {
            float pa[4][4];
            #pragma unroll
            for (int i = 0; i < 4; i++) {
                float4 pv = *(const float4*)&KP[(ty * 4 + i) * 68 + kk0];
                pa[i][0] = pv.x; pa[i][1] = pv.y; pa[i][2] = pv.z; pa[i][3] = pv.w;
            }
            #pragma unroll
            for (int t = 0; t < 4; t++) {
                float4 vv = *(const float4*)&Vs[(kk0 + t) * 64 + tx * 4];
                unsigned long long v01 = pack2(vv.x, vv.y);
                unsigned long long v23 = pack2(vv.z, vv.w);
                #pragma unroll
                for (int i = 0; i < 4; i++) {
                    unsigned long long pd = pack2(pa[i][t], pa[i][t]);
                    Op[i][0] = ffma2(pd, v01, Op[i][0]);
                    Op[i][1] = ffma2(pd, v23, Op[i][1]);
                }
            }
        }
    }

    // reduce row sums across the 16 tx lanes (xor over lane bits 0..3 only)
    #pragma unroll
    for (int i = 0; i < 4; i++) {
        float v = lsum[i];
        #pragma unroll
        for (int off = 1; off < 16; off <<= 1)
            v += __shfl_xor_sync(0xffffffffu, v, off);
        lsum[i] = v;
    }

    #pragma unroll
    for (int i = 0; i < 4; i++) {
        const float rinv = 1.0f / lsum[i];
        if (tx == 0)
            g_Linv[(size_t)bh * SS + q0 + ty * 4 + i] = rinv;
        float o0, o1, o2, o3;
        unpack2(Op[i][0], o0, o1);
        unpack2(Op[i][1], o2, o3);
        float4 o = make_float4(o0 * rinv, o1 * rinv, o2 * rinv, o3 * rinv);
        *(float4*)&g_X[((size_t)b * SS + q0 + ty * 4 + i) * HH + h * HDD + tx * 4] = o;
    }
}

// ---------------------------------------------------------------------------
// Normalize attention in place: attn[row, :] *= 1/l[row]
// ---------------------------------------------------------------------------
__global__ void rescale_kernel(float4* __restrict__ attn)
{
    const size_t n4 = (size_t)BB * NHH * SS * (SS / 4);
    size_t i = (size_t)blockIdx.x * blockDim.x + threadIdx.x;
    const size_t stride = (size_t)gridDim.x * blockDim.x;
    for (; i < n4; i += stride) {
        const size_t row = i >> 10;          // / (SS/4)
        const float r = __ldg(&g_Linv[row]);
        float4 v = attn[i];
        v.x *= r; v.y *= r; v.z *= r; v.w *= r;
        attn[i] = v;
    }
}

// ---------------------------------------------------------------------------
extern "C" void kernel_launch(void* const* d_in, const int* in_sizes, int n_in,
                              void* d_out, int out_size)
{
    const float* q  = (const float*)d_in[0];
    const float* k  = (const float*)d_in[1];
    const float* v  = (const float*)d_in[2];
    const float* Wq = (const float*)d_in[3];
    const float* bq = (const float*)d_in[4];
    const float* Wk = (const float*)d_in[5];
    const float* bk = (const float*)d_in[6];
    const float* Wv = (const float*)d_in[7];
    const float* bv = (const float*)d_in[8];
    const float* Wo = (const float*)d_in[9];
    const float* bo = (const float*)d_in[10];

    float *pQ, *pK, *pV, *pX, *pY;
    cudaGetSymbolAddress((void**)&pQ, g_Qh);
    cudaGetSymbolAddress((void**)&pK, g_Kh);
    cudaGetSymbolAddress((void**)&pV, g_Vh);
    cudaGetSymbolAddress((void**)&pX, g_X);
    cudaGetSymbolAddress((void**)&pY, g_Y);

    const long long X_ELEMS = (long long)BB * SS * HH;                 // 4,194,304
    const long long A_ELEMS = (long long)BB * NHH * SS * (long long)SS; // 268,435,456
    const long long osz = (long long)out_size;

    float* xout = nullptr;
    float* attn = nullptr;
    if (osz >= X_ELEMS + A_ELEMS) {            // tuple (x, attention)
        xout = (float*)d_out;
        attn = (float*)d_out + X_ELEMS;
    } else if (osz == A_ELEMS) {               // attention only
        attn = (float*)d_out;
    } else {                                   // x only
        xout = (float*)d_out;
    }

    const dim3 gproj(128, 8);
    gemm_bias_kernel<<<gproj, 256>>>(q, Wq, bq, pQ, 1);
    gemm_bias_kernel<<<gproj, 256>>>(k, Wk, bk, pK, 1);
    gemm_bias_kernel<<<gproj, 256>>>(v, Wv, bv, pV, 1);

    cudaFuncSetAttribute(attn_kernel, cudaFuncAttributeMaxDynamicSharedMemorySize, 51200);
    attn_kernel<<<dim3(64, 8, 2), 256, 51200>>>(attn);

    gemm_bias_kernel<<<gproj, 256>>>(pX, Wo, bo, xout ? xout : pY, 0);

    if (attn)
        rescale_kernel<<<16384, 256>>>((float4*)attn);
}

// round 17
// speedup vs baseline: 1.0508x; 1.0008x over previous
#include <cuda_runtime.h>

#define BB  2
#define SS  4096
#define HH  512
#define NHH 8
#define HDD 64

// ---------------- f32x2 packed-math helpers (sm_103a FFMA2 path) -----------
// Each f32x2 lane does the identical RN fp32 FMA as scalar FFMA, so pairing
// accumulators along j keeps every accumulator's reduction order bitwise
// identical to the scalar version.
__device__ __forceinline__ unsigned long long ffma2(unsigned long long a,
                                                    unsigned long long b,
                                                    unsigned long long c) {
    unsigned long long d;
    asm("fma.rn.f32x2 %0, %1, %2, %3;" : "=l"(d) : "l"(a), "l"(b), "l"(c));
    return d;
}
__device__ __forceinline__ unsigned long long pack2(float lo, float hi) {
    unsigned long long d;
    asm("mov.b64 %0, {%1, %2};" : "=l"(d) : "f"(lo), "f"(hi));
    return d;
}
__device__ __forceinline__ void unpack2(unsigned long long d, float& lo, float& hi) {
    asm("mov.b64 {%0, %1}, %2;" : "=f"(lo), "=f"(hi) : "l"(d));
}

// ---------------- scratch (device globals; no cudaMalloc allowed) ----------
__device__ float g_Qh[(size_t)BB * NHH * SS * HDD];   // [B,NH,S,HD]
__device__ float g_Kh[(size_t)BB * NHH * SS * HDD];
__device__ float g_Vh[(size_t)BB * NHH * SS * HDD];
__device__ float g_X [(size_t)BB * SS * HH];          // attention out, flat [B,S,H]
__device__ float g_Y [(size_t)BB * SS * HH];          // final proj scratch if x not requested
__device__ float g_Linv[(size_t)BB * NHH * SS];       // 1/rowsum per attention row

// ---------------------------------------------------------------------------
// GEMM: out = A @ W^T + bias.  A:[8192,512] row-major, W:[512,512] row-major.
// headLayout=1: out[((b*NH+h)*S+s)*HD+d]  (h = blockIdx.y since tile width 64 == HD)
// headLayout=0: out[m*H + n] flat.
// 64x64 tile, 256 threads, 4x4 per thread, K-step 16, FFMA2 inner product.
// ---------------------------------------------------------------------------
__global__ void __launch_bounds__(256)
gemm_bias_kernel(const float* __restrict__ A, const float* __restrict__ W,
                 const float* __restrict__ bias, float* __restrict__ out,
                 int headLayout)
{
    __shared__ float As[16 * 68];   // [k][m], padded stride 68 (16B-aligned rows)
    __shared__ float Ws[16 * 68];   // [k][n]

    const int tid = threadIdx.x;
    const int tx  = tid & 15;
    const int ty  = tid >> 4;
    const int m0  = blockIdx.x * 64;
    const int n0  = blockIdx.y * 64;
    const int lm  = tid >> 2;          // 0..63
    const int lk  = (tid & 3) << 2;    // 0,4,8,12

    unsigned long long acc[4][2] = {};   // pairs over j: (j0,j1),(j2,j3)

    for (int k0 = 0; k0 < HH; k0 += 16) {
        float4 a = *(const float4*)&A[(size_t)(m0 + lm) * HH + k0 + lk];
        float4 w = *(const float4*)&W[(size_t)(n0 + lm) * HH + k0 + lk];
        __syncthreads();
        As[(lk + 0) * 68 + lm] = a.x; As[(lk + 1) * 68 + lm] = a.y;
        As[(lk + 2) * 68 + lm] = a.z; As[(lk + 3) * 68 + lm] = a.w;
        Ws[(lk + 0) * 68 + lm] = w.x; Ws[(lk + 1) * 68 + lm] = w.y;
        Ws[(lk + 2) * 68 + lm] = w.z; Ws[(lk + 3) * 68 + lm] = w.w;
        __syncthreads();
        #pragma unroll
        for (int kk = 0; kk < 16; kk++) {
            float4 av = *(const float4*)&As[kk * 68 + ty * 4];
            float4 wv = *(const float4*)&Ws[kk * 68 + tx * 4];
            unsigned long long w01 = pack2(wv.x, wv.y);
            unsigned long long w23 = pack2(wv.z, wv.w);
            float aa[4] = {av.x, av.y, av.z, av.w};
            #pragma unroll
            for (int i = 0; i < 4; i++) {
                unsigned long long ad = pack2(aa[i], aa[i]);
                acc[i][0] = ffma2(ad, w01, acc[i][0]);
                acc[i][1] = ffma2(ad, w23, acc[i][1]);
            }
        }
    }

    float4 bv = *(const float4*)&bias[n0 + tx * 4];
    float ba[4] = {bv.x, bv.y, bv.z, bv.w};

    #pragma unroll
    for (int i = 0; i < 4; i++) {
        const int m = m0 + ty * 4 + i;
        float c0, c1, c2, c3;
        unpack2(acc[i][0], c0, c1);
        unpack2(acc[i][1], c2, c3);
        float4 o = make_float4(c0 + ba[0], c1 + ba[1], c2 + ba[2], c3 + ba[3]);
        if (headLayout) {
            const int b = m >> 12;          // m / 4096
            const int s = m & 4095;
            *(float4*)&out[(((size_t)(b * NHH + blockIdx.y)) * SS + s) * HDD + tx * 4] = o;
        } else {
            *(float4*)&out[(size_t)m * HH + n0 + tx * 4] = o;
        }
    }
}

// ---------------------------------------------------------------------------
// Attention: per block = one (b,h) x 64-query tile, sweep all 4096 keys in
// 64-wide K tiles.  Single pass (max-free softmax is exact: shift-invariant,
// |score| << 88 so exp never overflows).  Writes unnormalized exp scores to
// attn (normalized later), accumulates rowsum l and O = P @ V, writes O/l
// directly in flat [B,S,H] layout, and stores 1/l for the rescale kernel.
// Both GEMM loops use fma.rn.f32x2 (FFMA2): halves fma-pipe instruction
// count — the measured bottleneck (scalar version ran at the exact 36 TF/s
// FFMA-3reg rt=2 roofline). Accumulator pairing is along j, so reduction
// order per accumulator is bitwise identical to the scalar kernel.
// ---------------------------------------------------------------------------
__global__ void __launch_bounds__(256)
attn_kernel(float* __restrict__ attn)   // may be null -> skip attention stores
{
    extern __shared__ float sm[];
    float* Qs = sm;                 // Qs[d*68 + r]
    float* KP = sm + 64 * 68;       // scores: KP[d*68 + c] ; AV: KP[r*68 + k]
    float* Vs = sm + 2 * 64 * 68;   // Vs[k*64 + d]

    const int tid = threadIdx.x;
    const int tx  = tid & 15;
    const int ty  = tid >> 4;
    const int qt  = blockIdx.x;
    const int h   = blockIdx.y;
    const int b   = blockIdx.z;
    const int bh  = b * NHH + h;
    const int q0  = qt * 64;

    const float* __restrict__ Qg = g_Qh + ((size_t)bh * SS + q0) * HDD;
    const float* __restrict__ Kg = g_Kh + (size_t)bh * SS * HDD;
    const float* __restrict__ Vg = g_Vh + (size_t)bh * SS * HDD;

    // Q tile -> smem, transposed to d-major
    #pragma unroll
    for (int it = 0; it < 4; it++) {
        int idx = tid + it * 256;
        int r   = idx >> 4;
        int d0  = (idx & 15) << 2;
        float4 t = *(const float4*)&Qg[(size_t)r * HDD + d0];
        Qs[(d0 + 0) * 68 + r] = t.x;
        Qs[(d0 + 1) * 68 + r] = t.y;
        Qs[(d0 + 2) * 68 + r] = t.z;
        Qs[(d0 + 3) * 68 + r] = t.w;
    }

    unsigned long long Op[4][2] = {};   // O accumulator pairs over j
    float lsum[4]  = {};

    for (int kt = 0; kt < 64; kt++) {
        const int s0 = kt * 64;
        __syncthreads();   // prev AV done (and first iter: Q stores visible)

        // K tile transposed -> KP, V tile -> Vs
        #pragma unroll
        for (int it = 0; it < 4; it++) {
            int idx = tid + it * 256;
            int r   = idx >> 4;
            int d0  = (idx & 15) << 2;
            float4 t = *(const float4*)&Kg[(size_t)(s0 + r) * HDD + d0];
            KP[(d0 + 0) * 68 + r] = t.x;
            KP[(d0 + 1) * 68 + r] = t.y;
            KP[(d0 + 2) * 68 + r] = t.z;
            KP[(d0 + 3) * 68 + r] = t.w;
            float4 u = *(const float4*)&Vg[(size_t)(s0 + r) * HDD + d0];
            *(float4*)&Vs[r * 64 + d0] = u;
        }
        __syncthreads();

        // scores: S = Q K^T  (rank-1 updates over d; FFMA2 pairs over j)
        unsigned long long pp[4][2] = {};
        #pragma unroll 8
        for (int d = 0; d < 64; d++) {
            float4 qv = *(const float4*)&Qs[d * 68 + ty * 4];
            float4 kv = *(const float4*)&KP[d * 68 + tx * 4];
            unsigned long long k01 = pack2(kv.x, kv.y);
            unsigned long long k23 = pack2(kv.z, kv.w);
            float qa[4] = {qv.x, qv.y, qv.z, qv.w};
            #pragma unroll
            for (int i = 0; i < 4; i++) {
                unsigned long long qd = pack2(qa[i], qa[i]);
                pp[i][0] = ffma2(qd, k01, pp[i][0]);
                pp[i][1] = ffma2(qd, k23, pp[i][1]);
            }
        }

        // exp(scale * s), rowsum, unnormalized attention store
        float p[4][4];
        #pragma unroll
        for (int i = 0; i < 4; i++) {
            unpack2(pp[i][0], p[i][0], p[i][1]);
            unpack2(pp[i][1], p[i][2], p[i][3]);
            #pragma unroll
            for (int j = 0; j < 4; j++)
                p[i][j] = __expf(p[i][j] * 0.125f);   // 1/sqrt(64)
            lsum[i] += p[i][0] + p[i][1] + p[i][2] + p[i][3];
            if (attn)
                *(float4*)&attn[((size_t)bh * SS + q0 + ty * 4 + i) * SS + s0 + tx * 4]
                    = make_float4(p[i][0], p[i][1], p[i][2], p[i][3]);
        }

        __syncthreads();   // everyone done reading K from KP
        #pragma unroll
        for (int i = 0; i < 4; i++)
            *(float4*)&KP[(ty * 4 + i) * 68 + tx * 4]
                = make_float4(p[i][0], p[i][1], p[i][2], p[i][3]);
        __syncthreads();

        // O += P @ V, grouped 4 keys per step; FFMA2 pairs over j.
        #pragma unroll 4
        for (int kk0 = 0; kk0 < 64; kk0 += 4) {
            float pa[4][4];
            #pragma unroll
            for (int i = 0; i < 4; i++) {
                float4 pv = *(const float4*)&KP[(ty * 4 + i) * 68 + kk0];
                pa[i][0] = pv.x; pa[i][1] = pv.y; pa[i][2] = pv.z; pa[i][3] = pv.w;
            }
            #pragma unroll
            for (int t = 0; t < 4; t++) {
                float4 vv = *(const float4*)&Vs[(kk0 + t) * 64 + tx * 4];
                unsigned long long v01 = pack2(vv.x, vv.y);
                unsigned long long v23 = pack2(vv.z, vv.w);
                #pragma unroll
                for (int i = 0; i < 4; i++) {
                    unsigned long long pd = pack2(pa[i][t], pa[i][t]);
                    Op[i][0] = ffma2(pd, v01, Op[i][0]);
                    Op[i][1] = ffma2(pd, v23, Op[i][1]);
                }
            }
        }
    }

    // reduce row sums across the 16 tx lanes (xor over lane bits 0..3 only)
    #pragma unroll
    for (int i = 0; i < 4; i++) {
        float v = lsum[i];
        #pragma unroll
        for (int off = 1; off < 16; off <<= 1)
            v += __shfl_xor_sync(0xffffffffu, v, off);
        lsum[i] = v;
    }

    #pragma unroll
    for (int i = 0; i < 4; i++) {
        const float rinv = 1.0f / lsum[i];
        if (tx == 0)
            g_Linv[(size_t)bh * SS + q0 + ty * 4 + i] = rinv;
        float o0, o1, o2, o3;
        unpack2(Op[i][0], o0, o1);
        unpack2(Op[i][1], o2, o3);
        float4 o = make_float4(o0 * rinv, o1 * rinv, o2 * rinv, o3 * rinv);
        *(float4*)&g_X[((size_t)b * SS + q0 + ty * 4 + i) * HH + h * HDD + tx * 4] = o;
    }
}

// ---------------------------------------------------------------------------
// Normalize attention in place: attn[row, :] *= 1/l[row]
// ---------------------------------------------------------------------------
__global__ void rescale_kernel(float4* __restrict__ attn)
{
    const size_t n4 = (size_t)BB * NHH * SS * (SS / 4);
    size_t i = (size_t)blockIdx.x * blockDim.x + threadIdx.x;
    const size_t stride = (size_t)gridDim.x * blockDim.x;
    for (; i < n4; i += stride) {
        const size_t row = i >> 10;          // / (SS/4)
        const float r = __ldg(&g_Linv[row]);
        float4 v = attn[i];
        v.x *= r; v.y *= r; v.z *= r; v.w *= r;
        attn[i] = v;
    }
}

// ---------------------------------------------------------------------------
extern "C" void kernel_launch(void* const* d_in, const int* in_sizes, int n_in,
                              void* d_out, int out_size)
{
    const float* q  = (const float*)d_in[0];
    const float* k  = (const float*)d_in[1];
    const float* v  = (const float*)d_in[2];
    const float* Wq = (const float*)d_in[3];
    const float* bq = (const float*)d_in[4];
    const float* Wk = (const float*)d_in[5];
    const float* bk = (const float*)d_in[6];
    const float* Wv = (const float*)d_in[7];
    const float* bv = (const float*)d_in[8];
    const float* Wo = (const float*)d_in[9];
    const float* bo = (const float*)d_in[10];

    float *pQ, *pK, *pV, *pX, *pY;
    cudaGetSymbolAddress((void**)&pQ, g_Qh);
    cudaGetSymbolAddress((void**)&pK, g_Kh);
    cudaGetSymbolAddress((void**)&pV, g_Vh);
    cudaGetSymbolAddress((void**)&pX, g_X);
    cudaGetSymbolAddress((void**)&pY, g_Y);

    const long long X_ELEMS = (long long)BB * SS * HH;                 // 4,194,304
    const long long A_ELEMS = (long long)BB * NHH * SS * (long long)SS; // 268,435,456
    const long long osz = (long long)out_size;

    float* xout = nullptr;
    float* attn = nullptr;
    if (osz >= X_ELEMS + A_ELEMS) {            // tuple (x, attention)
        xout = (float*)d_out;
        attn = (float*)d_out + X_ELEMS;
    } else if (osz == A_ELEMS) {               // attention only
        attn = (float*)d_out;
    } else {                                   // x only
        xout = (float*)d_out;
    }

    const dim3 gproj(128, 8);
    gemm_bias_kernel<<<gproj, 256>>>(q, Wq, bq, pQ, 1);
    gemm_bias_kernel<<<gproj, 256>>>(k, Wk, bk, pK, 1);
    gemm_bias_kernel<<<gproj, 256>>>(v, Wv, bv, pV, 1);

    cudaFuncSetAttribute(attn_kernel, cudaFuncAttributeMaxDynamicSharedMemorySize, 51200);
    attn_kernel<<<dim3(64, 8, 2), 256, 51200>>>(attn);

    gemm_bias_kernel<<<gproj, 256>>>(pX, Wo, bo, xout ? xout : pY, 0);

    if (attn)
        rescale_kernel<<<16384, 256>>>((float4*)attn);
}